// round 5
// baseline (speedup 1.0000x reference)
#include <cuda_runtime.h>
#include <cstdint>

#define NB 16
#define TT 128
#define VV 64
#define FF 16
#define TCH 8                    // timesteps per smem chunk
#define NCH (TT / TCH)           // 16 chunks
#define PADF 20                  // padded feature stride (80B, 16B-aligned)
#define JPB 8                    // j-columns per CTA

// ---------------------------------------------------------------------------
// Fully fused kernel. CTA = (n, 8 j-columns). 512 threads = 64 i-lanes x 8
// t-groups. Each thread's chunk prefetch IS its own (tg, i) feature row:
// the LDG registers feed both the STS (so other threads can j-broadcast it)
// and, negated, the i-operand of the math — zero i-row LDS traffic.
// Math: packed f32x2 add2 + 2xLOP3(|.|) + fma2 per 2 features.
// Epilogue combines 8 t-groups in reused smem, exp(relu(mean)), column-
// normalizes over i, writes out[n,i,j]. One kernel, no scratch gmem.
// ---------------------------------------------------------------------------
__global__ __launch_bounds__(512, 1) void gl_fused_kernel(
    const float* __restrict__ x, const float* __restrict__ a,
    float* __restrict__ out)
{
    __shared__ __align__(16) float tile[TCH][VV][PADF];   // 40 KB (reused as part[])
    __shared__ float E[JPB][VV + 1];
    __shared__ float cinv[JPB];

    const int n     = blockIdx.y;
    const int jbase = blockIdx.x * JPB;
    const int tid   = threadIdx.x;
    const int i     = tid & 63;
    const int tg    = tid >> 6;       // t-group 0..7 (warp-uniform)

    // Pack a[f] coefficient pairs into f32x2 (low 32 bits = even f).
    uint64_t af2[8];
#pragma unroll
    for (int k = 0; k < 8; k++) {
        af2[k] = (uint64_t)__float_as_uint(__ldg(&a[2 * k])) |
                 ((uint64_t)__float_as_uint(__ldg(&a[2 * k + 1])) << 32);
    }

    // This thread's gmem row for chunk c: x[n, c*8 + tg, i, 0..15]  (64B).
    // Warp lanes are consecutive i -> fully coalesced 2KB LDG per warp.
    const float4* src = (const float4*)(x + (size_t)n * TT * VV * FF)
                        + ((size_t)tg * VV + i) * 4;

    union { float4 f4[4]; uint64_t u64[8]; } pre;
#pragma unroll
    for (int k = 0; k < 4; k++) pre.f4[k] = src[k];       // prefetch chunk 0

    uint64_t acc[JPB];
#pragma unroll
    for (int jj = 0; jj < JPB; jj++) acc[jj] = 0ull;

#pragma unroll 1
    for (int c = 0; c < NCH; c++) {
        __syncthreads();              // previous chunk's consumers done
#pragma unroll
        for (int k = 0; k < 4; k++)   // stage own row for j-broadcast reads
            *(float4*)&tile[tg][i][k * 4] = pre.f4[k];

        // i-operand straight from registers, pre-negated (add2 instead of sub).
        uint64_t nzi[8];
#pragma unroll
        for (int p = 0; p < 8; p++)
            nzi[p] = pre.u64[p] ^ 0x8000000080000000ULL;

        if (c + 1 < NCH) {            // prefetch next chunk (overlaps compute)
#pragma unroll
            for (int k = 0; k < 4; k++)
                pre.f4[k] = src[(size_t)(c + 1) * 2048 + k];
        }
        __syncthreads();              // STS visible to whole CTA

#pragma unroll
        for (int jj = 0; jj < JPB; jj++) {
            // j-row is warp-uniform (tg uniform, jj compile-time): LDS broadcast.
            const ulonglong2* zjr = (const ulonglong2*)&tile[tg][jbase + jj][0];
            ulonglong2 q0 = zjr[0], q1 = zjr[1], q2 = zjr[2], q3 = zjr[3];
            uint64_t zj[8] = {q0.x, q0.y, q1.x, q1.y, q2.x, q2.y, q3.x, q3.y};
#pragma unroll
            for (int p = 0; p < 8; p++) {
                uint64_t d;
                asm("add.rn.f32x2 %0, %1, %2;"
                    : "=l"(d) : "l"(nzi[p]), "l"(zj[p]));
                d &= 0x7FFFFFFF7FFFFFFFULL;           // packed |d| (2x LOP3)
                asm("fma.rn.f32x2 %0, %1, %2, %3;"
                    : "=l"(acc[jj]) : "l"(af2[p]), "l"(d), "l"(acc[jj]));
            }
        }
    }

    // ---- Epilogue: combine 8 t-groups, exp(relu(mean)), normalize over i ----
    __syncthreads();                  // done reading tile; reuse as part[]
    float* part = (float*)tile;       // part[tg][i][9] : stride 9 -> conflict-free
#pragma unroll
    for (int jj = 0; jj < JPB; jj++) {
        float r = __uint_as_float((unsigned)acc[jj]) +
                  __uint_as_float((unsigned)(acc[jj] >> 32));
        part[((size_t)tg * VV + i) * 9 + jj] = r;
    }
    __syncthreads();

    {   // thread -> (i2, jj2); sum the 8 t-group partials
        const int i2  = tid & 63;
        const int jj2 = tid >> 6;
        float s = 0.f;
#pragma unroll
        for (int g = 0; g < 8; g++)
            s += part[((size_t)g * VV + i2) * 9 + jj2];
        E[jj2][i2] = expf(fmaxf(s * (1.0f / (float)TT), 0.f));
    }
    __syncthreads();

    {   // warps 0..7: column sum over all 64 i for column w
        const int w = tid >> 5, lane = tid & 31;
        if (w < JPB) {
            float v = E[w][lane] + E[w][lane + 32];
#pragma unroll
            for (int o = 16; o; o >>= 1) v += __shfl_xor_sync(0xffffffffu, v, o);
            if (lane == 0) cinv[w] = 1.0f / v;
        }
    }
    __syncthreads();

    {   // write out[n][io][jbase+jo]; 8 consecutive floats per io
        const int io = tid >> 3;
        const int jo = tid & 7;
        out[(size_t)n * VV * VV + io * VV + jbase + jo] = E[jo][io] * cinv[jo];
    }
}

extern "C" void kernel_launch(void* const* d_in, const int* in_sizes, int n_in,
                              void* d_out, int out_size)
{
    const float* x = (const float*)d_in[0];       // [16,128,64,16] fp32
    const float* a = (const float*)d_in[1];       // [16,1] fp32
    float* out = (float*)d_out;                   // [16,64,64] fp32

    gl_fused_kernel<<<dim3(VV / JPB, NB), 512>>>(x, a, out);
}

// round 6
// speedup vs baseline: 1.5903x; 1.5903x over previous
#include <cuda_runtime.h>
#include <cstdint>

#define NB 16
#define TT 128
#define VV 64
#define FF 16
#define TBL 8                    // timesteps per k1 block
#define NTB (TT / TBL)           // 16 t-blocks
#define NK 32                    // k-offsets (pairs (i, i+k), k=1..32)
#define PADF 20                  // padded feature stride (80B, 16B-aligned)

// scratch[slice][n][k-1][i]  (16*16*32*64 floats = 2 MB)
__device__ __align__(16) float g_part[NTB * NB * NK * VV];

// ---------------------------------------------------------------------------
// Kernel 1 (symmetric): for k=1..32, partial[tb][n][k-1][i] =
//   sum over 8 timesteps, 16 feats of a[f] * |x[t,i,f] - x[t,(i+k)%64,f]|
// Each unordered vertex pair {i,j} computed ONCE (k=32 double-covered).
// 256 thr = 64 i-lanes x 4 k-groups; thread owns (i, 8 k) -> 8 scalar accs.
// Math: packed f32x2 add2 + 2xLOP3(|.|) + fma2 per 2 features.
// ---------------------------------------------------------------------------
__global__ __launch_bounds__(256, 2) void gl_partial_kernel(
    const float* __restrict__ x, const float* __restrict__ a)
{
    __shared__ __align__(16) float tile[TBL][VV][PADF];   // 40 KB

    const int n  = blockIdx.y;
    const int tb = blockIdx.x;
    const int tid = threadIdx.x;
    const int i   = tid & 63;
    const int kg  = tid >> 6;         // k-group 0..3 (warp-uniform)

    // Load tile: x[n, tb*8 : +8, :, :] contiguous (8192 floats).
    const float4* src = (const float4*)(x + (size_t)(n * TT + tb * TBL) * VV * FF);
#pragma unroll
    for (int q = tid; q < TBL * VV * 4; q += 256) {
        float4 v = src[q];
        int t  = q >> 8;              // 256 float4 per timestep
        int r  = q & 255;
        int vv = r >> 2;
        int f4 = r & 3;
        *(float4*)&tile[t][vv][f4 * 4] = v;
    }

    // Pack a[f] coefficient pairs into f32x2 (low 32 bits = even f).
    uint64_t af2[8];
#pragma unroll
    for (int k = 0; k < 8; k++) {
        af2[k] = (uint64_t)__float_as_uint(__ldg(&a[2 * k])) |
                 ((uint64_t)__float_as_uint(__ldg(&a[2 * k + 1])) << 32);
    }
    __syncthreads();

    uint64_t acc[8];
#pragma unroll
    for (int kk = 0; kk < 8; kk++) acc[kk] = 0ull;

#pragma unroll 1                      // body ~4.8KB: fits L0 I$
    for (int t = 0; t < TBL; t++) {
        // i-row: lane-varying LDS.128 x4, conflict-free (stride 80B), negated.
        const ulonglong2* zr = (const ulonglong2*)&tile[t][i][0];
        ulonglong2 zi0 = zr[0], zi1 = zr[1], zi2 = zr[2], zi3 = zr[3];
        uint64_t nzi[8];
        nzi[0] = zi0.x ^ 0x8000000080000000ULL;
        nzi[1] = zi0.y ^ 0x8000000080000000ULL;
        nzi[2] = zi1.x ^ 0x8000000080000000ULL;
        nzi[3] = zi1.y ^ 0x8000000080000000ULL;
        nzi[4] = zi2.x ^ 0x8000000080000000ULL;
        nzi[5] = zi2.y ^ 0x8000000080000000ULL;
        nzi[6] = zi3.x ^ 0x8000000080000000ULL;
        nzi[7] = zi3.y ^ 0x8000000080000000ULL;

#pragma unroll
        for (int kk = 0; kk < 8; kk++) {
            const int j = (i + kg * 8 + kk + 1) & 63;   // partner vertex
            // j-row: lane-varying (consecutive rows mod 64) -> conflict-free.
            const ulonglong2* zjr = (const ulonglong2*)&tile[t][j][0];
            ulonglong2 q0 = zjr[0], q1 = zjr[1], q2 = zjr[2], q3 = zjr[3];
            uint64_t zj[8] = {q0.x, q0.y, q1.x, q1.y, q2.x, q2.y, q3.x, q3.y};
#pragma unroll
            for (int p = 0; p < 8; p++) {
                uint64_t d;
                asm("add.rn.f32x2 %0, %1, %2;"
                    : "=l"(d) : "l"(nzi[p]), "l"(zj[p]));
                d &= 0x7FFFFFFF7FFFFFFFULL;             // packed |d| (2x LOP3)
                asm("fma.rn.f32x2 %0, %1, %2, %3;"
                    : "=l"(acc[kk]) : "l"(af2[p]), "l"(d), "l"(acc[kk]));
            }
        }
    }

    // Store: g_part[tb][n][kg*8+kk][i]; lanes i-consecutive -> 256B coalesced.
    float* outp = &g_part[(((size_t)tb * NB + n) * NK + kg * 8) * VV + i];
#pragma unroll
    for (int kk = 0; kk < 8; kk++) {
        float r = __uint_as_float((unsigned)acc[kk]) +
                  __uint_as_float((unsigned)(acc[kk] >> 32));
        outp[kk * VV] = r;
    }
}

// ---------------------------------------------------------------------------
// Kernel 2: one CTA per n (512 threads). Reduce 16 slices of the triangular
// representation, e = exp(relu(mean)), expand to symmetric E[64][64],
// column-normalize over i, write out[n,i,j].
// ---------------------------------------------------------------------------
__global__ __launch_bounds__(512) void gl_finalize_kernel(float* __restrict__ out)
{
    __shared__ float E[VV][VV + 2];   // [i][j], pad 66 -> conflict-light
    __shared__ float cinv[VV];

    const int n   = blockIdx.x;
    const int tid = threadIdx.x;

    // Phase A: reduce over 16 slices. Thread t owns float4 t of the n-block:
    // (k = t>>4, i = (t&15)*4). 16 independent LDGs (MLP 16, L2-resident).
    {
        const float4* g4 = (const float4*)g_part;
        const int base = n * (NK * VV / 4) + tid;        // n*512 + t
        const int sstride = NB * NK * VV / 4;            // 8192 float4/slice
        float4 s = make_float4(0.f, 0.f, 0.f, 0.f);
#pragma unroll
        for (int sl = 0; sl < NTB; sl++) {
            float4 v = g4[(size_t)sl * sstride + base];
            s.x += v.x; s.y += v.y; s.z += v.z; s.w += v.w;
        }
        const float inv = 1.0f / (float)TT;
        const int k_act = (tid >> 4) + 1;                // actual k (1..32)
        const int i0    = (tid & 15) * 4;
        float e[4] = { expf(fmaxf(s.x * inv, 0.f)), expf(fmaxf(s.y * inv, 0.f)),
                       expf(fmaxf(s.z * inv, 0.f)), expf(fmaxf(s.w * inv, 0.f)) };
#pragma unroll
        for (int q = 0; q < 4; q++) {
            int ii = i0 + q;
            int jj = (ii + k_act) & 63;
            E[ii][jj] = e[q];
            E[jj][ii] = e[q];
        }
        if (tid < VV) E[tid][tid] = 1.0f;               // diag: exp(relu(0))
    }
    __syncthreads();

    // Phase B: column sums over i (16 warps x 4 columns each).
    {
        const int w = tid >> 5, lane = tid & 31;
#pragma unroll
        for (int c = 0; c < 4; c++) {
            int j = w * 4 + c;
            float v = E[lane][j] + E[lane + 32][j];
#pragma unroll
            for (int o = 16; o; o >>= 1) v += __shfl_xor_sync(0xffffffffu, v, o);
            if (lane == 0) cinv[j] = 1.0f / v;
        }
    }
    __syncthreads();

    // Phase C: out[n][i][j] = E[i][j] * cinv[j], float4 stores.
    {
        const int i  = tid >> 3;
        const int jb = (tid & 7) * 8;
        float4 w0, w1;
        w0.x = E[i][jb + 0] * cinv[jb + 0];
        w0.y = E[i][jb + 1] * cinv[jb + 1];
        w0.z = E[i][jb + 2] * cinv[jb + 2];
        w0.w = E[i][jb + 3] * cinv[jb + 3];
        w1.x = E[i][jb + 4] * cinv[jb + 4];
        w1.y = E[i][jb + 5] * cinv[jb + 5];
        w1.z = E[i][jb + 6] * cinv[jb + 6];
        w1.w = E[i][jb + 7] * cinv[jb + 7];
        float* o = out + (size_t)n * VV * VV + i * VV + jb;
        *(float4*)o       = w0;
        *(float4*)(o + 4) = w1;
    }
}

extern "C" void kernel_launch(void* const* d_in, const int* in_sizes, int n_in,
                              void* d_out, int out_size)
{
    const float* x = (const float*)d_in[0];       // [16,128,64,16] fp32
    const float* a = (const float*)d_in[1];       // [16,1] fp32
    float* out = (float*)d_out;                   // [16,64,64] fp32

    gl_partial_kernel<<<dim3(NTB, NB), 256>>>(x, a);
    gl_finalize_kernel<<<NB, 512>>>(out);
}

// round 7
// speedup vs baseline: 1.7733x; 1.1151x over previous
#include <cuda_runtime.h>
#include <cstdint>

#define NB 16
#define TT 128
#define VV 64
#define FF 16
#define TBL 8                    // timesteps per k1 block
#define NTB (TT / TBL)           // 16 t-blocks
#define NK 32                    // k-offsets (pairs (i, i+k), k=1..32)
#define PADF 20                  // padded feature stride (80B, 16B-aligned)

// scratch[slice][n][k-1][i]  (16*16*32*64 floats = 2 MB)
__device__ __align__(16) float g_part[NTB * NB * NK * VV];

// Parity swizzle: even logical rows -> physical 0..31, odd -> 32..63.
// Makes even-stride lane patterns conflict-free (phys stride 20 words).
__device__ __forceinline__ int prow(int r) {
    r &= 63;
    return (r >> 1) + ((r & 1) << 5);
}

// ---------------------------------------------------------------------------
// Kernel 1 (symmetric, 2-wide i blocking): for k=1..32,
//   partial[tb][n][k-1][i] = sum_{8 t, 16 f} a[f] * |x[t,i,f] - x[t,(i+k)%64,f]|
// 256 thr = (32 even-i0 lanes x 4 k-groups) x 2 t-slots. Thread owns i-rows
// {i0, i0+1} and k = k0+1..k0+8: j-rows i0+k0+1..i0+k0+9 (9 loads serve 16
// pairs). Slot partials combined in smem before one gmem store.
// ---------------------------------------------------------------------------
__global__ __launch_bounds__(256, 2) void gl_partial_kernel(
    const float* __restrict__ x, const float* __restrict__ a)
{
    __shared__ __align__(16) float tile[TBL][VV][PADF];   // 40 KB

    const int n   = blockIdx.y;
    const int tb  = blockIdx.x;
    const int tid = threadIdx.x;
    const int q    = tid & 127;       // pair-thread id
    const int slot = tid >> 7;        // t-slot 0/1
    const int i0   = (q & 31) * 2;    // even base vertex
    const int k0   = (q >> 5) * 8;    // k-group base (0,8,16,24)

    // Load tile (swizzled rows): x[n, tb*8 : +8, :, :] contiguous.
    const float4* src = (const float4*)(x + (size_t)(n * TT + tb * TBL) * VV * FF);
#pragma unroll
    for (int w = tid; w < TBL * VV * 4; w += 256) {
        float4 v = src[w];
        int t  = w >> 8;
        int r  = w & 255;
        int vv = r >> 2;
        int f4 = r & 3;
        *(float4*)&tile[t][prow(vv)][f4 * 4] = v;
    }

    // Pack a[f] pairs into f32x2 (low 32 bits = even f).
    uint64_t af2[8];
#pragma unroll
    for (int k = 0; k < 8; k++) {
        af2[k] = (uint64_t)__float_as_uint(__ldg(&a[2 * k])) |
                 ((uint64_t)__float_as_uint(__ldg(&a[2 * k + 1])) << 32);
    }
    __syncthreads();

    uint64_t acc[2][8];
#pragma unroll
    for (int m = 0; m < 2; m++)
#pragma unroll
        for (int d = 0; d < 8; d++) acc[m][d] = 0ull;

#pragma unroll 1
    for (int tt = 0; tt < 4; tt++) {
        const int t = slot * 4 + tt;
        // i-rows (phys: i0>>1 and i0>>1 + 32), negated for add2-based sub.
        uint64_t nzi[2][8];
#pragma unroll
        for (int m = 0; m < 2; m++) {
            const ulonglong2* zr =
                (const ulonglong2*)&tile[t][(i0 >> 1) + m * 32][0];
            ulonglong2 z0 = zr[0], z1 = zr[1], z2 = zr[2], z3 = zr[3];
            nzi[m][0] = z0.x ^ 0x8000000080000000ULL;
            nzi[m][1] = z0.y ^ 0x8000000080000000ULL;
            nzi[m][2] = z1.x ^ 0x8000000080000000ULL;
            nzi[m][3] = z1.y ^ 0x8000000080000000ULL;
            nzi[m][4] = z2.x ^ 0x8000000080000000ULL;
            nzi[m][5] = z2.y ^ 0x8000000080000000ULL;
            nzi[m][6] = z3.x ^ 0x8000000080000000ULL;
            nzi[m][7] = z3.y ^ 0x8000000080000000ULL;
        }

#pragma unroll
        for (int r = 1; r <= 9; r++) {
            // j-row (i0+k0+r) mod 64, parity-swizzled: conflict-free.
            const ulonglong2* zjr =
                (const ulonglong2*)&tile[t][prow(i0 + k0 + r)][0];
            ulonglong2 w0 = zjr[0], w1 = zjr[1], w2 = zjr[2], w3 = zjr[3];
            uint64_t zj[8] = {w0.x, w0.y, w1.x, w1.y, w2.x, w2.y, w3.x, w3.y};
            if (r <= 8) {             // pair (i0, i0+k0+r) -> acc[0][r-1]
#pragma unroll
                for (int p = 0; p < 8; p++) {
                    uint64_t d;
                    asm("add.rn.f32x2 %0, %1, %2;"
                        : "=l"(d) : "l"(nzi[0][p]), "l"(zj[p]));
                    d &= 0x7FFFFFFF7FFFFFFFULL;
                    asm("fma.rn.f32x2 %0, %1, %2, %3;"
                        : "=l"(acc[0][r - 1]) : "l"(af2[p]), "l"(d), "l"(acc[0][r - 1]));
                }
            }
            if (r >= 2) {             // pair (i0+1, i0+k0+r) -> acc[1][r-2]
#pragma unroll
                for (int p = 0; p < 8; p++) {
                    uint64_t d;
                    asm("add.rn.f32x2 %0, %1, %2;"
                        : "=l"(d) : "l"(nzi[1][p]), "l"(zj[p]));
                    d &= 0x7FFFFFFF7FFFFFFFULL;
                    asm("fma.rn.f32x2 %0, %1, %2, %3;"
                        : "=l"(acc[1][r - 2]) : "l"(af2[p]), "l"(d), "l"(acc[1][r - 2]));
                }
            }
        }
    }

    // Reduce packed halves to scalar per (m,d).
    float s[2][8];
#pragma unroll
    for (int m = 0; m < 2; m++)
#pragma unroll
        for (int d = 0; d < 8; d++)
            s[m][d] = __uint_as_float((unsigned)acc[m][d]) +
                      __uint_as_float((unsigned)(acc[m][d] >> 32));

    // Combine the two t-slots in (reused) smem, then slot 0 stores.
    __syncthreads();
    float* red = (float*)tile;        // 128 threads x 16 floats = 8 KB
    if (slot == 1) {
#pragma unroll
        for (int m = 0; m < 2; m++)
#pragma unroll
            for (int d = 0; d < 8; d++)
                red[q * 16 + m * 8 + d] = s[m][d];
    }
    __syncthreads();
    if (slot == 0) {
        float* outp = &g_part[(((size_t)tb * NB + n) * NK + k0) * VV + i0];
#pragma unroll
        for (int d = 0; d < 8; d++) {
            float2 w;
            w.x = s[0][d] + red[q * 16 + d];          // vertex i0,   k=k0+d+1
            w.y = s[1][d] + red[q * 16 + 8 + d];      // vertex i0+1, k=k0+d+1
            *(float2*)(outp + (size_t)d * VV) = w;    // [k-1][i0..i0+1]
        }
    }
}

// ---------------------------------------------------------------------------
// Kernel 2: one CTA per n (512 threads). Reduce 16 slices with forced MLP-16,
// e = exp(relu(mean)), expand to symmetric E, column-normalize, store.
// ---------------------------------------------------------------------------
__global__ __launch_bounds__(512) void gl_finalize_kernel(float* __restrict__ out)
{
    __shared__ float E[VV][VV + 2];
    __shared__ float cinv[VV];

    const int n   = blockIdx.x;
    const int tid = threadIdx.x;

    {   // Phase A: 16 independent loads -> tree sum (MLP 16).
        const float4* g4 = (const float4*)g_part;
        const int base = n * (NK * VV / 4) + tid;
        const int sstride = NB * NK * VV / 4;
        float4 v[NTB];
#pragma unroll
        for (int sl = 0; sl < NTB; sl++)
            v[sl] = g4[(size_t)sl * sstride + base];
#pragma unroll
        for (int st = 8; st; st >>= 1)
#pragma unroll
            for (int sl = 0; sl < st; sl++) {
                v[sl].x += v[sl + st].x; v[sl].y += v[sl + st].y;
                v[sl].z += v[sl + st].z; v[sl].w += v[sl + st].w;
            }
        const float inv = 1.0f / (float)TT;
        const int k_act = (tid >> 4) + 1;
        const int i0    = (tid & 15) * 4;
        float e[4] = { expf(fmaxf(v[0].x * inv, 0.f)), expf(fmaxf(v[0].y * inv, 0.f)),
                       expf(fmaxf(v[0].z * inv, 0.f)), expf(fmaxf(v[0].w * inv, 0.f)) };
#pragma unroll
        for (int p = 0; p < 4; p++) {
            int ii = i0 + p;
            int jj = (ii + k_act) & 63;
            E[ii][jj] = e[p];
            E[jj][ii] = e[p];
        }
        if (tid < VV) E[tid][tid] = 1.0f;             // diag: exp(relu(0))
    }
    __syncthreads();

    {   // Phase B: column sums over i (16 warps x 4 columns).
        const int w = tid >> 5, lane = tid & 31;
#pragma unroll
        for (int c = 0; c < 4; c++) {
            int j = w * 4 + c;
            float v = E[lane][j] + E[lane + 32][j];
#pragma unroll
            for (int o = 16; o; o >>= 1) v += __shfl_xor_sync(0xffffffffu, v, o);
            if (lane == 0) cinv[j] = 1.0f / v;
        }
    }
    __syncthreads();

    {   // Phase C: out[n][i][j] = E[i][j] * cinv[j], 2x float4 stores.
        const int i  = tid >> 3;
        const int jb = (tid & 7) * 8;
        float4 w0, w1;
        w0.x = E[i][jb + 0] * cinv[jb + 0];
        w0.y = E[i][jb + 1] * cinv[jb + 1];
        w0.z = E[i][jb + 2] * cinv[jb + 2];
        w0.w = E[i][jb + 3] * cinv[jb + 3];
        w1.x = E[i][jb + 4] * cinv[jb + 4];
        w1.y = E[i][jb + 5] * cinv[jb + 5];
        w1.z = E[i][jb + 6] * cinv[jb + 6];
        w1.w = E[i][jb + 7] * cinv[jb + 7];
        float* o = out + (size_t)n * VV * VV + i * VV + jb;
        *(float4*)o       = w0;
        *(float4*)(o + 4) = w1;
    }
}

extern "C" void kernel_launch(void* const* d_in, const int* in_sizes, int n_in,
                              void* d_out, int out_size)
{
    const float* x = (const float*)d_in[0];       // [16,128,64,16] fp32
    const float* a = (const float*)d_in[1];       // [16,1] fp32
    float* out = (float*)d_out;                   // [16,64,64] fp32

    gl_partial_kernel<<<dim3(NTB, NB), 256>>>(x, a);
    gl_finalize_kernel<<<NB, 512>>>(out);
}